// round 2
// baseline (speedup 1.0000x reference)
#include <cuda_runtime.h>
#include <cuda_bf16.h>
#include <stdint.h>

// ---------------------------------------------------------------------------
// Fused grayscale + 8x8 DCT(4x4 kept) + 2-layer MLP + transpose-store kernel.
// One block = 128 patches (one image, two patch-rows). MLP on bf16 tensor
// cores with 3-term error-compensated split (hi*hi + hi*lo + lo*hi) so the
// result matches fp32 to ~1e-5 relative.
// ---------------------------------------------------------------------------

namespace {

constexpr int BLOCK = 128;
constexpr int IMG   = 512;

// padded strides (in bf16 elements unless noted)
constexpr int FK  = 20;    // feats / W1T k-stride
constexpr int W2K = 264;   // W2T k-stride
constexpr int HBS = 72;    // h-buffer row stride
constexpr int EBS = 65;    // emb staging row stride (fp32 elements)

// shared memory byte offsets
constexpr int SZ_W1  = 256 * FK * 2;         // 10240
constexpr int SZ_W2  = 64 * W2K * 2;         // 33792
constexpr int SZ_F   = 128 * FK * 2;         // 5120
constexpr int OFF_W1H = 0;
constexpr int OFF_W1L = OFF_W1H + SZ_W1;
constexpr int OFF_W2H = OFF_W1L + SZ_W1;     // 20480
constexpr int OFF_W2L = OFF_W2H + SZ_W2;
constexpr int OFF_FH  = OFF_W2L + SZ_W2;     // 88064
constexpr int OFF_FL  = OFF_FH + SZ_F;
constexpr int OFF_B1  = OFF_FL + SZ_F;       // 98304
constexpr int OFF_B2  = OFF_B1 + 256 * 4;
constexpr int OFF_HB  = OFF_B2 + 64 * 4;     // 99584 (16B aligned)
constexpr int SZ_HB   = 4 * 2 * 32 * HBS * 2; // 36864 (also holds emb staging: 128*65*4=33280)
constexpr int SMEM_TOTAL = OFF_HB + SZ_HB;    // 136448

__device__ __forceinline__ void mma_bf16(float c[4], const uint32_t a[4],
                                         uint32_t b0, uint32_t b1) {
    asm volatile(
        "mma.sync.aligned.m16n8k16.row.col.f32.bf16.bf16.f32 "
        "{%0,%1,%2,%3}, {%4,%5,%6,%7}, {%8,%9}, {%0,%1,%2,%3};"
        : "+f"(c[0]), "+f"(c[1]), "+f"(c[2]), "+f"(c[3])
        : "r"(a[0]), "r"(a[1]), "r"(a[2]), "r"(a[3]), "r"(b0), "r"(b1));
}

__device__ __forceinline__ uint32_t pack_split_hi(float v0, float v1,
                                                  uint32_t& lo_out) {
    __nv_bfloat162 h2 = __floats2bfloat162_rn(v0, v1);
    float l0 = v0 - __bfloat162float(__low2bfloat16(h2));
    float l1 = v1 - __bfloat162float(__high2bfloat16(h2));
    __nv_bfloat162 l2 = __floats2bfloat162_rn(l0, l1);
    lo_out = *reinterpret_cast<uint32_t*>(&l2);
    return *reinterpret_cast<uint32_t*>(&h2);
}

__global__ void __launch_bounds__(BLOCK, 1)
dct_mlp_kernel(const float* __restrict__ x, const float* __restrict__ W1,
               const float* __restrict__ b1, const float* __restrict__ W2,
               const float* __restrict__ b2, float* __restrict__ out)
{
    extern __shared__ char smem[];
    __nv_bfloat16* sW1h = reinterpret_cast<__nv_bfloat16*>(smem + OFF_W1H);
    __nv_bfloat16* sW1l = reinterpret_cast<__nv_bfloat16*>(smem + OFF_W1L);
    __nv_bfloat16* sW2h = reinterpret_cast<__nv_bfloat16*>(smem + OFF_W2H);
    __nv_bfloat16* sW2l = reinterpret_cast<__nv_bfloat16*>(smem + OFF_W2L);
    __nv_bfloat16* sFh  = reinterpret_cast<__nv_bfloat16*>(smem + OFF_FH);
    __nv_bfloat16* sFl  = reinterpret_cast<__nv_bfloat16*>(smem + OFF_FL);
    float* sB1 = reinterpret_cast<float*>(smem + OFF_B1);
    float* sB2 = reinterpret_cast<float*>(smem + OFF_B2);

    const int tid  = threadIdx.x;
    const int warp = tid >> 5;
    const int lane = tid & 31;
    const int b    = blockIdx.x >> 5;   // image
    const int rp   = blockIdx.x & 31;   // patch-row pair (gy = 2*rp .. 2*rp+1)

    // ---------------- stage weights (split bf16, transposed) ----------------
    {
        const float4* w1v = reinterpret_cast<const float4*>(W1);
        #pragma unroll
        for (int i = tid; i < 1024; i += BLOCK) {   // 16*256/4
            float4 v = w1v[i];
            int k = (i * 4) >> 8, n = (i * 4) & 255;
            float vv[4] = {v.x, v.y, v.z, v.w};
            #pragma unroll
            for (int q = 0; q < 4; q++) {
                __nv_bfloat16 h = __float2bfloat16_rn(vv[q]);
                sW1h[(n + q) * FK + k] = h;
                sW1l[(n + q) * FK + k] = __float2bfloat16_rn(vv[q] - __bfloat162float(h));
            }
        }
        const float4* w2v = reinterpret_cast<const float4*>(W2);
        for (int i = tid; i < 4096; i += BLOCK) {   // 256*64/4
            float4 v = w2v[i];
            int k = (i * 4) >> 6, n = (i * 4) & 63;
            float vv[4] = {v.x, v.y, v.z, v.w};
            #pragma unroll
            for (int q = 0; q < 4; q++) {
                __nv_bfloat16 h = __float2bfloat16_rn(vv[q]);
                sW2h[(n + q) * W2K + k] = h;
                sW2l[(n + q) * W2K + k] = __float2bfloat16_rn(vv[q] - __bfloat162float(h));
            }
        }
        for (int i = tid; i < 256; i += BLOCK) sB1[i] = b1[i];
        if (tid < 64) sB2[tid] = b2[tid];
    }

    // ---------------- DCT: one patch per thread ------------------------------
    {
        const float D4[4][8] = {
            { 0.35355339059327373f, 0.35355339059327373f, 0.35355339059327373f, 0.35355339059327373f,
              0.35355339059327373f, 0.35355339059327373f, 0.35355339059327373f, 0.35355339059327373f},
            { 0.49039264020161522f, 0.41573480615127262f, 0.27778511650980114f, 0.09754516100806412f,
             -0.09754516100806412f,-0.27778511650980114f,-0.41573480615127262f,-0.49039264020161522f},
            { 0.46193976625564337f, 0.19134171618254492f,-0.19134171618254492f,-0.46193976625564337f,
             -0.46193976625564337f,-0.19134171618254492f, 0.19134171618254492f, 0.46193976625564337f},
            { 0.41573480615127262f,-0.09754516100806412f,-0.49039264020161522f,-0.27778511650980114f,
              0.27778511650980114f, 0.49039264020161522f, 0.09754516100806412f,-0.41573480615127262f}
        };
        const int gyl = tid >> 6, gx = tid & 63;
        const int gy = rp * 2 + gyl;
        const size_t plane = (size_t)IMG * IMG;
        const float* base = x + (size_t)b * 3 * plane + (size_t)(gy * 8) * IMG + gx * 8;

        float tmp[4][8];
        #pragma unroll
        for (int k = 0; k < 4; k++)
            #pragma unroll
            for (int j = 0; j < 8; j++) tmp[k][j] = 0.f;

        #pragma unroll
        for (int i = 0; i < 8; i++) {
            const float4* r0 = reinterpret_cast<const float4*>(base + (size_t)i * IMG);
            const float4* r1 = reinterpret_cast<const float4*>(base + plane + (size_t)i * IMG);
            const float4* r2 = reinterpret_cast<const float4*>(base + 2 * plane + (size_t)i * IMG);
            float4 ra = __ldcs(r0),     rb = __ldcs(r0 + 1);
            float4 ga = __ldcs(r1),     gb = __ldcs(r1 + 1);
            float4 ba = __ldcs(r2),     bb = __ldcs(r2 + 1);
            float g[8];
            g[0] = 0.299f * ra.x + 0.587f * ga.x + 0.114f * ba.x;
            g[1] = 0.299f * ra.y + 0.587f * ga.y + 0.114f * ba.y;
            g[2] = 0.299f * ra.z + 0.587f * ga.z + 0.114f * ba.z;
            g[3] = 0.299f * ra.w + 0.587f * ga.w + 0.114f * ba.w;
            g[4] = 0.299f * rb.x + 0.587f * gb.x + 0.114f * bb.x;
            g[5] = 0.299f * rb.y + 0.587f * gb.y + 0.114f * bb.y;
            g[6] = 0.299f * rb.z + 0.587f * gb.z + 0.114f * bb.z;
            g[7] = 0.299f * rb.w + 0.587f * gb.w + 0.114f * bb.w;
            #pragma unroll
            for (int k = 0; k < 4; k++)
                #pragma unroll
                for (int j = 0; j < 8; j++)
                    tmp[k][j] = fmaf(D4[k][i], g[j], tmp[k][j]);
        }
        // coeffs[k][l] = sum_j tmp[k][j]*D4[l][j]; feats index n = 4k+l
        uint32_t* fhW = reinterpret_cast<uint32_t*>(sFh) + tid * (FK / 2);
        uint32_t* flW = reinterpret_cast<uint32_t*>(sFl) + tid * (FK / 2);
        #pragma unroll
        for (int k = 0; k < 4; k++) {
            #pragma unroll
            for (int l = 0; l < 4; l += 2) {
                float c0 = 0.f, c1 = 0.f;
                #pragma unroll
                for (int j = 0; j < 8; j++) {
                    c0 = fmaf(tmp[k][j], D4[l][j], c0);
                    c1 = fmaf(tmp[k][j], D4[l + 1][j], c1);
                }
                uint32_t lo, hi = pack_split_hi(c0, c1, lo);
                int w = (4 * k + l) >> 1;   // word index (n even)
                fhW[w] = hi;
                flW[w] = lo;
            }
        }
    }

    __syncthreads();

    // ---------------- MLP on tensor cores ------------------------------------
    const int g = lane >> 2, t = lane & 3;
    const uint32_t* w1hW = reinterpret_cast<const uint32_t*>(sW1h);
    const uint32_t* w1lW = reinterpret_cast<const uint32_t*>(sW1l);
    const uint32_t* w2hW = reinterpret_cast<const uint32_t*>(sW2h);
    const uint32_t* w2lW = reinterpret_cast<const uint32_t*>(sW2l);
    const uint32_t* fhW  = reinterpret_cast<const uint32_t*>(sFh);
    const uint32_t* flW  = reinterpret_cast<const uint32_t*>(sFl);
    uint32_t* hbh = reinterpret_cast<uint32_t*>(smem + OFF_HB) + warp * 2 * 32 * (HBS / 2);
    uint32_t* hbl = hbh + 32 * (HBS / 2);

    // A1 fragments (feats, K=16 = one k-step), persistent
    uint32_t A1h[2][4], A1l[2][4];
    #pragma unroll
    for (int mt = 0; mt < 2; mt++) {
        int r0 = warp * 32 + mt * 16 + g;
        A1h[mt][0] = fhW[r0 * 10 + t];
        A1h[mt][1] = fhW[(r0 + 8) * 10 + t];
        A1h[mt][2] = fhW[r0 * 10 + t + 4];
        A1h[mt][3] = fhW[(r0 + 8) * 10 + t + 4];
        A1l[mt][0] = flW[r0 * 10 + t];
        A1l[mt][1] = flW[(r0 + 8) * 10 + t];
        A1l[mt][2] = flW[r0 * 10 + t + 4];
        A1l[mt][3] = flW[(r0 + 8) * 10 + t + 4];
    }

    // emb accumulators, init from b2
    float acc2[2][8][4];
    #pragma unroll
    for (int nt = 0; nt < 8; nt++) {
        float v0 = sB2[nt * 8 + 2 * t], v1 = sB2[nt * 8 + 2 * t + 1];
        #pragma unroll
        for (int mt = 0; mt < 2; mt++) {
            acc2[mt][nt][0] = v0; acc2[mt][nt][1] = v1;
            acc2[mt][nt][2] = v0; acc2[mt][nt][3] = v1;
        }
    }

    #pragma unroll
    for (int ch = 0; ch < 4; ch++) {
        // ---- layer 1: h chunk [32 rows x 64 hidden] per warp ----
        #pragma unroll
        for (int nt = 0; nt < 8; nt++) {
            const int n0 = ch * 64 + nt * 8;
            uint32_t B1h0 = w1hW[(n0 + g) * 10 + t];
            uint32_t B1h1 = w1hW[(n0 + g) * 10 + t + 4];
            uint32_t B1l0 = w1lW[(n0 + g) * 10 + t];
            uint32_t B1l1 = w1lW[(n0 + g) * 10 + t + 4];
            float bias0 = sB1[n0 + 2 * t], bias1 = sB1[n0 + 2 * t + 1];
            #pragma unroll
            for (int mt = 0; mt < 2; mt++) {
                float c[4] = {bias0, bias1, bias0, bias1};
                mma_bf16(c, A1h[mt], B1h0, B1h1);
                mma_bf16(c, A1h[mt], B1l0, B1l1);
                mma_bf16(c, A1l[mt], B1h0, B1h1);
                #pragma unroll
                for (int hh = 0; hh < 2; hh++) {
                    float v0 = fmaxf(c[hh * 2 + 0], 0.f);
                    float v1 = fmaxf(c[hh * 2 + 1], 0.f);
                    uint32_t lo, hi = pack_split_hi(v0, v1, lo);
                    int lr = mt * 16 + hh * 8 + g;
                    int wc = nt * 4 + t;
                    hbh[lr * 36 + wc] = hi;
                    hbl[lr * 36 + wc] = lo;
                }
            }
        }
        __syncwarp();
        // ---- layer 2 partial: K-chunk of 64 (4 k-steps of 16) ----
        #pragma unroll
        for (int ks = 0; ks < 4; ks++) {
            uint32_t A2h[2][4], A2l[2][4];
            #pragma unroll
            for (int mt = 0; mt < 2; mt++) {
                int r0 = mt * 16 + g;
                int wc = ks * 8 + t;
                A2h[mt][0] = hbh[r0 * 36 + wc];
                A2h[mt][1] = hbh[(r0 + 8) * 36 + wc];
                A2h[mt][2] = hbh[r0 * 36 + wc + 4];
                A2h[mt][3] = hbh[(r0 + 8) * 36 + wc + 4];
                A2l[mt][0] = hbl[r0 * 36 + wc];
                A2l[mt][1] = hbl[(r0 + 8) * 36 + wc];
                A2l[mt][2] = hbl[r0 * 36 + wc + 4];
                A2l[mt][3] = hbl[(r0 + 8) * 36 + wc + 4];
            }
            const int kb = (ch * 64 + ks * 16) >> 1;  // word base
            #pragma unroll
            for (int nt = 0; nt < 8; nt++) {
                uint32_t B2h0 = w2hW[(nt * 8 + g) * 132 + kb + t];
                uint32_t B2h1 = w2hW[(nt * 8 + g) * 132 + kb + t + 4];
                uint32_t B2l0 = w2lW[(nt * 8 + g) * 132 + kb + t];
                uint32_t B2l1 = w2lW[(nt * 8 + g) * 132 + kb + t + 4];
                #pragma unroll
                for (int mt = 0; mt < 2; mt++) {
                    mma_bf16(acc2[mt][nt], A2h[mt], B2h0, B2h1);
                    mma_bf16(acc2[mt][nt], A2h[mt], B2l0, B2l1);
                    mma_bf16(acc2[mt][nt], A2l[mt], B2h0, B2h1);
                }
            }
        }
        __syncwarp();
    }

    // ---------------- epilogue: stage emb, coalesced store -------------------
    __syncthreads();   // everyone done with hbuf; reuse region as fp32 staging
    float* sEmb = reinterpret_cast<float*>(smem + OFF_HB);
    #pragma unroll
    for (int mt = 0; mt < 2; mt++) {
        int r = warp * 32 + mt * 16 + g;
        #pragma unroll
        for (int nt = 0; nt < 8; nt++) {
            int c = nt * 8 + 2 * t;
            sEmb[r * EBS + c]           = acc2[mt][nt][0];
            sEmb[r * EBS + c + 1]       = acc2[mt][nt][1];
            sEmb[(r + 8) * EBS + c]     = acc2[mt][nt][2];
            sEmb[(r + 8) * EBS + c + 1] = acc2[mt][nt][3];
        }
    }
    __syncthreads();
    // out[((b*64 + c)*64 + gy)*64 + gx] ; gy*64+gx = rp*128 + tid
    float* ob = out + (size_t)b * 64 * 4096 + rp * 128 + tid;
    #pragma unroll 8
    for (int c = 0; c < 64; c++)
        ob[(size_t)c * 4096] = sEmb[tid * EBS + c];
}

} // anonymous namespace

extern "C" void kernel_launch(void* const* d_in, const int* in_sizes, int n_in,
                              void* d_out, int out_size) {
    const float* x  = (const float*)d_in[0];
    const float* W1 = (const float*)d_in[1];
    const float* b1 = (const float*)d_in[2];
    const float* W2 = (const float*)d_in[3];
    const float* b2 = (const float*)d_in[4];
    float* out = (float*)d_out;

    int B = in_sizes[0] / (3 * IMG * IMG);   // 32
    cudaFuncSetAttribute(dct_mlp_kernel,
                         cudaFuncAttributeMaxDynamicSharedMemorySize, SMEM_TOTAL);
    dct_mlp_kernel<<<B * 32, BLOCK, SMEM_TOTAL>>>(x, W1, b1, W2, b2, out);
}

// round 3
// speedup vs baseline: 1.7132x; 1.7132x over previous
#include <cuda_runtime.h>
#include <cuda_bf16.h>
#include <stdint.h>

// ---------------------------------------------------------------------------
// R3: fused gray+DCT+MLP with register-direct layer1->layer2 (no h smem),
// prep kernel for weight split/transpose, 256 thr / 2 blocks per SM.
// bf16 3-term error-compensated split (hi*hi + hi*lo + lo*hi).
// ---------------------------------------------------------------------------

namespace {

constexpr int IMG = 512;
constexpr int FK  = 20;    // feats / W1T row stride (bf16 elems, 16 used)
constexpr int W2K = 264;   // W2T row stride (bf16 elems, 256 used)

// prep/global + smem shared layout (byte offsets)
constexpr int P_W1H  = 0;                       // 256 x FK bf16 = 10240
constexpr int P_W1L  = 10240;
constexpr int P_W2H  = 20480;                   // 64 x W2K bf16 = 33792
constexpr int P_W2L  = 54272;
constexpr int P_B1   = 88064;                   // 256 f32
constexpr int P_B2   = 89088;                   // 64 f32
constexpr int P_TOTAL = 89344;                  // 16B multiple

constexpr int OFF_FH = P_TOTAL;                 // 128 x FK bf16 = 5120
constexpr int OFF_FL = OFF_FH + 5120;
constexpr int SMEM_TOTAL = OFF_FL + 5120;       // 99584 -> 2 blocks/SM

__device__ __align__(16) unsigned char gPrep[P_TOTAL];

__device__ __forceinline__ void mma_bf16(float c[4], const uint32_t a[4],
                                         uint32_t b0, uint32_t b1) {
    asm volatile(
        "mma.sync.aligned.m16n8k16.row.col.f32.bf16.bf16.f32 "
        "{%0,%1,%2,%3}, {%4,%5,%6,%7}, {%8,%9}, {%0,%1,%2,%3};"
        : "+f"(c[0]), "+f"(c[1]), "+f"(c[2]), "+f"(c[3])
        : "r"(a[0]), "r"(a[1]), "r"(a[2]), "r"(a[3]), "r"(b0), "r"(b1));
}

__device__ __forceinline__ uint32_t pack_split_hi(float v0, float v1,
                                                  uint32_t& lo_out) {
    __nv_bfloat162 h2 = __floats2bfloat162_rn(v0, v1);
    float l0 = v0 - __bfloat162float(__low2bfloat16(h2));
    float l1 = v1 - __bfloat162float(__high2bfloat16(h2));
    __nv_bfloat162 l2 = __floats2bfloat162_rn(l0, l1);
    lo_out = *reinterpret_cast<uint32_t*>(&l2);
    return *reinterpret_cast<uint32_t*>(&h2);
}

// ------------------------------ prep kernel --------------------------------
__global__ void prep_kernel(const float* __restrict__ W1, const float* __restrict__ b1,
                            const float* __restrict__ W2, const float* __restrict__ b2)
{
    int i = blockIdx.x * blockDim.x + threadIdx.x;
    __nv_bfloat16* w1h = reinterpret_cast<__nv_bfloat16*>(gPrep + P_W1H);
    __nv_bfloat16* w1l = reinterpret_cast<__nv_bfloat16*>(gPrep + P_W1L);
    __nv_bfloat16* w2h = reinterpret_cast<__nv_bfloat16*>(gPrep + P_W2H);
    __nv_bfloat16* w2l = reinterpret_cast<__nv_bfloat16*>(gPrep + P_W2L);
    if (i < 4096) {                        // W1 [16,256] row-major
        float v = W1[i];
        int k = i >> 8, n = i & 255;
        __nv_bfloat16 h = __float2bfloat16_rn(v);
        w1h[n * FK + k] = h;
        w1l[n * FK + k] = __float2bfloat16_rn(v - __bfloat162float(h));
    }
    if (i < 16384) {                       // W2 [256,64] row-major
        float v = W2[i];
        int k = i >> 6, n = i & 63;
        __nv_bfloat16 h = __float2bfloat16_rn(v);
        w2h[n * W2K + k] = h;
        w2l[n * W2K + k] = __float2bfloat16_rn(v - __bfloat162float(h));
    }
    if (i < 256) reinterpret_cast<float*>(gPrep + P_B1)[i] = b1[i];
    if (i < 64)  reinterpret_cast<float*>(gPrep + P_B2)[i] = b2[i];
}

// ------------------------------ main kernel --------------------------------
__global__ void __launch_bounds__(256, 2)
dct_mlp_kernel(const float* __restrict__ x, float* __restrict__ out)
{
    extern __shared__ char smem[];
    const int tid  = threadIdx.x;
    const int warp = tid >> 5;
    const int lane = tid & 31;
    const int b    = blockIdx.x >> 5;   // image
    const int rp   = blockIdx.x & 31;   // patch-row pair

    if (tid >= 128) {
        // warps 4-7: copy prepped weights+biases (L2-hot) into smem, linear.
        const int4* src = reinterpret_cast<const int4*>(gPrep);
        int4* dst = reinterpret_cast<int4*>(smem);
        #pragma unroll 4
        for (int i = tid - 128; i < P_TOTAL / 16; i += 128)
            dst[i] = src[i];
    } else {
        // warps 0-3: grayscale + DCT, one 8x8 patch per thread.
        const float D4[4][8] = {
            { 0.35355339059327373f, 0.35355339059327373f, 0.35355339059327373f, 0.35355339059327373f,
              0.35355339059327373f, 0.35355339059327373f, 0.35355339059327373f, 0.35355339059327373f},
            { 0.49039264020161522f, 0.41573480615127262f, 0.27778511650980114f, 0.09754516100806412f,
             -0.09754516100806412f,-0.27778511650980114f,-0.41573480615127262f,-0.49039264020161522f},
            { 0.46193976625564337f, 0.19134171618254492f,-0.19134171618254492f,-0.46193976625564337f,
             -0.46193976625564337f,-0.19134171618254492f, 0.19134171618254492f, 0.46193976625564337f},
            { 0.41573480615127262f,-0.09754516100806412f,-0.49039264020161522f,-0.27778511650980114f,
              0.27778511650980114f, 0.49039264020161522f, 0.09754516100806412f,-0.41573480615127262f}
        };
        const int gyl = tid >> 6, gx = tid & 63;
        const int gy = rp * 2 + gyl;
        const size_t plane = (size_t)IMG * IMG;
        const float* base = x + (size_t)b * 3 * plane + (size_t)(gy * 8) * IMG + gx * 8;

        float tmp[4][8];
        #pragma unroll
        for (int k = 0; k < 4; k++)
            #pragma unroll
            for (int j = 0; j < 8; j++) tmp[k][j] = 0.f;

        #pragma unroll
        for (int i = 0; i < 8; i++) {
            const float4* r0 = reinterpret_cast<const float4*>(base + (size_t)i * IMG);
            const float4* r1 = reinterpret_cast<const float4*>(base + plane + (size_t)i * IMG);
            const float4* r2 = reinterpret_cast<const float4*>(base + 2 * plane + (size_t)i * IMG);
            float4 ra = __ldcs(r0),     rb = __ldcs(r0 + 1);
            float4 ga = __ldcs(r1),     gb = __ldcs(r1 + 1);
            float4 ba = __ldcs(r2),     bb = __ldcs(r2 + 1);
            float g[8];
            g[0] = 0.299f * ra.x + 0.587f * ga.x + 0.114f * ba.x;
            g[1] = 0.299f * ra.y + 0.587f * ga.y + 0.114f * ba.y;
            g[2] = 0.299f * ra.z + 0.587f * ga.z + 0.114f * ba.z;
            g[3] = 0.299f * ra.w + 0.587f * ga.w + 0.114f * ba.w;
            g[4] = 0.299f * rb.x + 0.587f * gb.x + 0.114f * bb.x;
            g[5] = 0.299f * rb.y + 0.587f * gb.y + 0.114f * bb.y;
            g[6] = 0.299f * rb.z + 0.587f * gb.z + 0.114f * bb.z;
            g[7] = 0.299f * rb.w + 0.587f * gb.w + 0.114f * bb.w;
            #pragma unroll
            for (int k = 0; k < 4; k++)
                #pragma unroll
                for (int j = 0; j < 8; j++)
                    tmp[k][j] = fmaf(D4[k][i], g[j], tmp[k][j]);
        }
        uint32_t* fhW = reinterpret_cast<uint32_t*>(smem + OFF_FH) + tid * (FK / 2);
        uint32_t* flW = reinterpret_cast<uint32_t*>(smem + OFF_FL) + tid * (FK / 2);
        #pragma unroll
        for (int k = 0; k < 4; k++) {
            #pragma unroll
            for (int l = 0; l < 4; l += 2) {
                float c0 = 0.f, c1 = 0.f;
                #pragma unroll
                for (int j = 0; j < 8; j++) {
                    c0 = fmaf(tmp[k][j], D4[l][j], c0);
                    c1 = fmaf(tmp[k][j], D4[l + 1][j], c1);
                }
                uint32_t lo, hi = pack_split_hi(c0, c1, lo);
                int w = (4 * k + l) >> 1;
                fhW[w] = hi;
                flW[w] = lo;
            }
        }
    }

    __syncthreads();

    // ---------------- MLP: 16 patches per warp, register-direct L1->L2 ------
    const int g = lane >> 2, t = lane & 3;
    const uint32_t* w1hW = reinterpret_cast<const uint32_t*>(smem + P_W1H);
    const uint32_t* w1lW = reinterpret_cast<const uint32_t*>(smem + P_W1L);
    const uint32_t* w2hW = reinterpret_cast<const uint32_t*>(smem + P_W2H);
    const uint32_t* w2lW = reinterpret_cast<const uint32_t*>(smem + P_W2L);
    const float* sB1 = reinterpret_cast<const float*>(smem + P_B1);
    const float* sB2 = reinterpret_cast<const float*>(smem + P_B2);
    const uint32_t* fhW = reinterpret_cast<const uint32_t*>(smem + OFF_FH);
    const uint32_t* flW = reinterpret_cast<const uint32_t*>(smem + OFF_FL);

    // A1: feats fragment (K=16, single k-step), persistent
    uint32_t A1h[4], A1l[4];
    {
        const int r0 = warp * 16 + g;
        A1h[0] = fhW[r0 * 10 + t];       A1h[1] = fhW[(r0 + 8) * 10 + t];
        A1h[2] = fhW[r0 * 10 + t + 4];   A1h[3] = fhW[(r0 + 8) * 10 + t + 4];
        A1l[0] = flW[r0 * 10 + t];       A1l[1] = flW[(r0 + 8) * 10 + t];
        A1l[2] = flW[r0 * 10 + t + 4];   A1l[3] = flW[(r0 + 8) * 10 + t + 4];
    }

    // emb accumulators init from b2
    float acc2[8][4];
    #pragma unroll
    for (int nt = 0; nt < 8; nt++) {
        float v0 = sB2[nt * 8 + 2 * t], v1 = sB2[nt * 8 + 2 * t + 1];
        acc2[nt][0] = v0; acc2[nt][1] = v1; acc2[nt][2] = v0; acc2[nt][3] = v1;
    }

    #pragma unroll 1
    for (int ch = 0; ch < 4; ch++) {
        #pragma unroll
        for (int s = 0; s < 4; s++) {
            // layer1: two n-tiles forming one k16 step of h; relu+pack -> A2
            uint32_t A2h[4], A2l[4];
            #pragma unroll
            for (int par = 0; par < 2; par++) {
                const int n0 = ch * 64 + (s * 2 + par) * 8;
                uint32_t B1h0 = w1hW[(n0 + g) * 10 + t];
                uint32_t B1h1 = w1hW[(n0 + g) * 10 + t + 4];
                uint32_t B1l0 = w1lW[(n0 + g) * 10 + t];
                uint32_t B1l1 = w1lW[(n0 + g) * 10 + t + 4];
                float bias0 = sB1[n0 + 2 * t], bias1 = sB1[n0 + 2 * t + 1];
                float c[4] = {bias0, bias1, bias0, bias1};
                mma_bf16(c, A1h, B1h0, B1h1);
                mma_bf16(c, A1h, B1l0, B1l1);
                mma_bf16(c, A1l, B1h0, B1h1);
                float v0 = fmaxf(c[0], 0.f), v1 = fmaxf(c[1], 0.f);
                float v2 = fmaxf(c[2], 0.f), v3 = fmaxf(c[3], 0.f);
                A2h[par * 2 + 0] = pack_split_hi(v0, v1, A2l[par * 2 + 0]);
                A2h[par * 2 + 1] = pack_split_hi(v2, v3, A2l[par * 2 + 1]);
            }
            // layer2: consume this k16 step against all 8 output n-tiles
            const int kb = (ch * 64 + s * 16) >> 1;   // word index into W2 rows
            #pragma unroll
            for (int nt = 0; nt < 8; nt++) {
                uint32_t B2h0 = w2hW[(nt * 8 + g) * 132 + kb + t];
                uint32_t B2h1 = w2hW[(nt * 8 + g) * 132 + kb + t + 4];
                uint32_t B2l0 = w2lW[(nt * 8 + g) * 132 + kb + t];
                uint32_t B2l1 = w2lW[(nt * 8 + g) * 132 + kb + t + 4];
                mma_bf16(acc2[nt], A2h, B2h0, B2h1);
                mma_bf16(acc2[nt], A2h, B2l0, B2l1);
                mma_bf16(acc2[nt], A2l, B2h0, B2h1);
            }
        }
    }

    // ---------------- epilogue: direct register stores ----------------------
    // out[((b*64 + c)*64 + gy)*64 + gx]; patch index = rp*128 + warp*16 + row
    float* ob = out + (size_t)b * 262144 + rp * 128 + warp * 16;
    #pragma unroll
    for (int nt = 0; nt < 8; nt++) {
        const int c0 = nt * 8 + 2 * t;
        ob[(size_t)c0 * 4096 + g]           = acc2[nt][0];
        ob[(size_t)(c0 + 1) * 4096 + g]     = acc2[nt][1];
        ob[(size_t)c0 * 4096 + g + 8]       = acc2[nt][2];
        ob[(size_t)(c0 + 1) * 4096 + g + 8] = acc2[nt][3];
    }
}

} // anonymous namespace

extern "C" void kernel_launch(void* const* d_in, const int* in_sizes, int n_in,
                              void* d_out, int out_size) {
    const float* x  = (const float*)d_in[0];
    const float* W1 = (const float*)d_in[1];
    const float* b1 = (const float*)d_in[2];
    const float* W2 = (const float*)d_in[3];
    const float* b2 = (const float*)d_in[4];
    float* out = (float*)d_out;

    int B = in_sizes[0] / (3 * IMG * IMG);   // 32

    prep_kernel<<<64, 256>>>(W1, b1, W2, b2);

    cudaFuncSetAttribute(dct_mlp_kernel,
                         cudaFuncAttributeMaxDynamicSharedMemorySize, SMEM_TOTAL);
    dct_mlp_kernel<<<B * 32, 256, SMEM_TOTAL>>>(x, out);
}

// round 4
// speedup vs baseline: 1.9871x; 1.1599x over previous
#include <cuda_runtime.h>
#include <cuda_fp16.h>
#include <stdint.h>

// ---------------------------------------------------------------------------
// R4: fused gray+DCT+MLP. fp16 2-term weight split (activations unsplit fp16),
// 32 rows per warp (2 m-tiles) to halve W2 smem traffic, 256 patches/block.
// ---------------------------------------------------------------------------

namespace {

constexpr int IMG = 512;
constexpr int W1S = 24;    // W1 row stride in fp16 elems (12 words)
constexpr int W2S = 264;   // W2 row stride in fp16 elems (132 words)
constexpr int FS  = 12;    // feats row stride in 32-bit words

// byte offsets (shared between gPrep and smem)
constexpr int P_W1H  = 0;                      // 256*12 words = 12288 B
constexpr int P_W1L  = 12288;
constexpr int P_W2H  = 24576;                  // 64*132 words = 33792 B
constexpr int P_W2L  = 58368;
constexpr int P_B1   = 92160;                  // 256 f32
constexpr int P_B2   = 93184;                  // 64 f32
constexpr int P_TOTAL = 93440;                 // 16B multiple
constexpr int OFF_F  = P_TOTAL;                // 256*FS words = 12288 B
constexpr int SMEM_TOTAL = OFF_F + 12288;      // 105728 -> 2 blocks/SM

__device__ __align__(16) unsigned char gPrep[P_TOTAL];

__device__ __forceinline__ void mma_f16(float c[4], const uint32_t a[4],
                                        uint32_t b0, uint32_t b1) {
    asm volatile(
        "mma.sync.aligned.m16n8k16.row.col.f32.f16.f16.f32 "
        "{%0,%1,%2,%3}, {%4,%5,%6,%7}, {%8,%9}, {%0,%1,%2,%3};"
        : "+f"(c[0]), "+f"(c[1]), "+f"(c[2]), "+f"(c[3])
        : "r"(a[0]), "r"(a[1]), "r"(a[2]), "r"(a[3]), "r"(b0), "r"(b1));
}

__device__ __forceinline__ uint32_t pack_h2(float v0, float v1) {
    __half2 h = __floats2half2_rn(v0, v1);
    return *reinterpret_cast<uint32_t*>(&h);
}

// ------------------------------ prep kernel --------------------------------
__global__ void prep_kernel(const float* __restrict__ W1, const float* __restrict__ b1,
                            const float* __restrict__ W2, const float* __restrict__ b2)
{
    int i = blockIdx.x * blockDim.x + threadIdx.x;
    __half* w1h = reinterpret_cast<__half*>(gPrep + P_W1H);
    __half* w1l = reinterpret_cast<__half*>(gPrep + P_W1L);
    __half* w2h = reinterpret_cast<__half*>(gPrep + P_W2H);
    __half* w2l = reinterpret_cast<__half*>(gPrep + P_W2L);
    if (i < 4096) {                        // W1 [16,256]
        float v = W1[i];
        int k = i >> 8, n = i & 255;
        __half h = __float2half_rn(v);
        w1h[n * W1S + k] = h;
        w1l[n * W1S + k] = __float2half_rn(v - __half2float(h));
    }
    if (i < 16384) {                       // W2 [256,64]
        float v = W2[i];
        int k = i >> 6, n = i & 63;
        __half h = __float2half_rn(v);
        w2h[n * W2S + k] = h;
        w2l[n * W2S + k] = __float2half_rn(v - __half2float(h));
    }
    if (i < 256) reinterpret_cast<float*>(gPrep + P_B1)[i] = b1[i];
    if (i < 64)  reinterpret_cast<float*>(gPrep + P_B2)[i] = b2[i];
}

// ------------------------------ main kernel --------------------------------
__global__ void __launch_bounds__(256, 2)
dct_mlp_kernel(const float* __restrict__ x, float* __restrict__ out)
{
    extern __shared__ char smem[];
    const int tid  = threadIdx.x;
    const int warp = tid >> 5;
    const int lane = tid & 31;
    const int b    = blockIdx.x >> 4;   // image
    const int rp   = blockIdx.x & 15;   // group of 4 patch-rows

    // ---- stage prepped weights into smem (L2-hot linear copy) ----
    {
        const int4* src = reinterpret_cast<const int4*>(gPrep);
        int4* dst = reinterpret_cast<int4*>(smem);
        #pragma unroll 6
        for (int i = tid; i < P_TOTAL / 16; i += 256)
            dst[i] = src[i];
    }

    // ---- grayscale + DCT, one 8x8 patch per thread ----
    {
        const float D4[4][8] = {
            { 0.35355339059327373f, 0.35355339059327373f, 0.35355339059327373f, 0.35355339059327373f,
              0.35355339059327373f, 0.35355339059327373f, 0.35355339059327373f, 0.35355339059327373f},
            { 0.49039264020161522f, 0.41573480615127262f, 0.27778511650980114f, 0.09754516100806412f,
             -0.09754516100806412f,-0.27778511650980114f,-0.41573480615127262f,-0.49039264020161522f},
            { 0.46193976625564337f, 0.19134171618254492f,-0.19134171618254492f,-0.46193976625564337f,
             -0.46193976625564337f,-0.19134171618254492f, 0.19134171618254492f, 0.46193976625564337f},
            { 0.41573480615127262f,-0.09754516100806412f,-0.49039264020161522f,-0.27778511650980114f,
              0.27778511650980114f, 0.49039264020161522f, 0.09754516100806412f,-0.41573480615127262f}
        };
        const int gyl = tid >> 6, gx = tid & 63;
        const int gy = rp * 4 + gyl;
        const size_t plane = (size_t)IMG * IMG;
        const float* base = x + (size_t)b * 3 * plane + (size_t)(gy * 8) * IMG + gx * 8;

        float tmp[4][8];
        #pragma unroll
        for (int k = 0; k < 4; k++)
            #pragma unroll
            for (int j = 0; j < 8; j++) tmp[k][j] = 0.f;

        #pragma unroll
        for (int i = 0; i < 8; i++) {
            const float4* r0 = reinterpret_cast<const float4*>(base + (size_t)i * IMG);
            const float4* r1 = reinterpret_cast<const float4*>(base + plane + (size_t)i * IMG);
            const float4* r2 = reinterpret_cast<const float4*>(base + 2 * plane + (size_t)i * IMG);
            float4 ra = __ldcs(r0),     rb = __ldcs(r0 + 1);
            float4 ga = __ldcs(r1),     gb = __ldcs(r1 + 1);
            float4 ba = __ldcs(r2),     bb = __ldcs(r2 + 1);
            float g[8];
            g[0] = 0.299f * ra.x + 0.587f * ga.x + 0.114f * ba.x;
            g[1] = 0.299f * ra.y + 0.587f * ga.y + 0.114f * ba.y;
            g[2] = 0.299f * ra.z + 0.587f * ga.z + 0.114f * ba.z;
            g[3] = 0.299f * ra.w + 0.587f * ga.w + 0.114f * ba.w;
            g[4] = 0.299f * rb.x + 0.587f * gb.x + 0.114f * bb.x;
            g[5] = 0.299f * rb.y + 0.587f * gb.y + 0.114f * bb.y;
            g[6] = 0.299f * rb.z + 0.587f * gb.z + 0.114f * bb.z;
            g[7] = 0.299f * rb.w + 0.587f * gb.w + 0.114f * bb.w;
            #pragma unroll
            for (int k = 0; k < 4; k++)
                #pragma unroll
                for (int j = 0; j < 8; j++)
                    tmp[k][j] = fmaf(D4[k][i], g[j], tmp[k][j]);
        }
        uint32_t* fW = reinterpret_cast<uint32_t*>(smem + OFF_F) + tid * FS;
        #pragma unroll
        for (int k = 0; k < 4; k++) {
            #pragma unroll
            for (int l = 0; l < 4; l += 2) {
                float c0 = 0.f, c1 = 0.f;
                #pragma unroll
                for (int j = 0; j < 8; j++) {
                    c0 = fmaf(tmp[k][j], D4[l][j], c0);
                    c1 = fmaf(tmp[k][j], D4[l + 1][j], c1);
                }
                fW[(4 * k + l) >> 1] = pack_h2(c0, c1);
            }
        }
    }

    __syncthreads();

    // ---------------- MLP: 32 patches per warp (2 m-tiles) -------------------
    const int g = lane >> 2, t = lane & 3;
    const uint32_t* w1h = reinterpret_cast<const uint32_t*>(smem + P_W1H);
    const uint32_t* w1l = reinterpret_cast<const uint32_t*>(smem + P_W1L);
    const uint32_t* w2h = reinterpret_cast<const uint32_t*>(smem + P_W2H);
    const uint32_t* w2l = reinterpret_cast<const uint32_t*>(smem + P_W2L);
    const float* sB1 = reinterpret_cast<const float*>(smem + P_B1);
    const float* sB2 = reinterpret_cast<const float*>(smem + P_B2);
    const uint32_t* fW = reinterpret_cast<const uint32_t*>(smem + OFF_F);

    // A1: feats fragments (K=16, one k-step), persistent, hi-only
    uint32_t A1[2][4];
    #pragma unroll
    for (int mt = 0; mt < 2; mt++) {
        const int r0 = warp * 32 + mt * 16 + g;
        A1[mt][0] = fW[r0 * FS + t];
        A1[mt][1] = fW[(r0 + 8) * FS + t];
        A1[mt][2] = fW[r0 * FS + t + 4];
        A1[mt][3] = fW[(r0 + 8) * FS + t + 4];
    }

    float acc2[2][8][4];
    #pragma unroll
    for (int nt = 0; nt < 8; nt++) {
        float v0 = sB2[nt * 8 + 2 * t], v1 = sB2[nt * 8 + 2 * t + 1];
        #pragma unroll
        for (int mt = 0; mt < 2; mt++) {
            acc2[mt][nt][0] = v0; acc2[mt][nt][1] = v1;
            acc2[mt][nt][2] = v0; acc2[mt][nt][3] = v1;
        }
    }

    #pragma unroll 1
    for (int ch = 0; ch < 4; ch++) {
        #pragma unroll
        for (int s = 0; s < 4; s++) {
            // layer 1: one k16 step of h for both m-tiles
            uint32_t A2[2][4];
            #pragma unroll
            for (int par = 0; par < 2; par++) {
                const int n0 = ch * 64 + (s * 2 + par) * 8;
                const int wr = (n0 + g) * (W1S / 2);
                uint32_t B10 = w1h[wr + t],     B11 = w1h[wr + t + 4];
                uint32_t L10 = w1l[wr + t],     L11 = w1l[wr + t + 4];
                float bias0 = sB1[n0 + 2 * t], bias1 = sB1[n0 + 2 * t + 1];
                #pragma unroll
                for (int mt = 0; mt < 2; mt++) {
                    float c[4] = {bias0, bias1, bias0, bias1};
                    mma_f16(c, A1[mt], B10, B11);
                    mma_f16(c, A1[mt], L10, L11);
                    A2[mt][par * 2 + 0] = pack_h2(fmaxf(c[0], 0.f), fmaxf(c[1], 0.f));
                    A2[mt][par * 2 + 1] = pack_h2(fmaxf(c[2], 0.f), fmaxf(c[3], 0.f));
                }
            }
            // layer 2: consume this k16 step for all 8 n-tiles, both m-tiles
            const int kb = ch * 32 + s * 8;   // word index within W2 row
            #pragma unroll
            for (int nt = 0; nt < 8; nt++) {
                const int wr = (nt * 8 + g) * (W2S / 2);
                uint32_t B2h0 = w2h[wr + kb + t], B2h1 = w2h[wr + kb + t + 4];
                uint32_t B2l0 = w2l[wr + kb + t], B2l1 = w2l[wr + kb + t + 4];
                #pragma unroll
                for (int mt = 0; mt < 2; mt++) {
                    mma_f16(acc2[mt][nt], A2[mt], B2h0, B2h1);
                    mma_f16(acc2[mt][nt], A2[mt], B2l0, B2l1);
                }
            }
        }
    }

    // ---------------- epilogue: direct register stores ----------------------
    // patch index = rp*256 + warp*32 + mt*16 + row;  out[((b*64+c)*4096) + p]
    float* ob = out + (size_t)b * 262144 + rp * 256 + warp * 32;
    #pragma unroll
    for (int mt = 0; mt < 2; mt++) {
        float* obm = ob + mt * 16;
        #pragma unroll
        for (int nt = 0; nt < 8; nt++) {
            const int c0 = nt * 8 + 2 * t;
            obm[(size_t)c0 * 4096 + g]           = acc2[mt][nt][0];
            obm[(size_t)(c0 + 1) * 4096 + g]     = acc2[mt][nt][1];
            obm[(size_t)c0 * 4096 + g + 8]       = acc2[mt][nt][2];
            obm[(size_t)(c0 + 1) * 4096 + g + 8] = acc2[mt][nt][3];
        }
    }
}

} // anonymous namespace

extern "C" void kernel_launch(void* const* d_in, const int* in_sizes, int n_in,
                              void* d_out, int out_size) {
    const float* x  = (const float*)d_in[0];
    const float* W1 = (const float*)d_in[1];
    const float* b1 = (const float*)d_in[2];
    const float* W2 = (const float*)d_in[3];
    const float* b2 = (const float*)d_in[4];
    float* out = (float*)d_out;

    int B = in_sizes[0] / (3 * IMG * IMG);   // 32

    prep_kernel<<<64, 256>>>(W1, b1, W2, b2);

    cudaFuncSetAttribute(dct_mlp_kernel,
                         cudaFuncAttributeMaxDynamicSharedMemorySize, SMEM_TOTAL);
    dct_mlp_kernel<<<B * 16, 256, SMEM_TOTAL>>>(x, out);
}